// round 17
// baseline (speedup 1.0000x reference)
#include <cuda_runtime.h>
#include <cuda_fp16.h>
#include <cstdint>

#define B_ 32
#define S_ 1024
#define D_ 512
#define SCALE 0.044194173824159216f   // 1/sqrt(512)

// masked_vec scratch (pre-softmax scores) + per-row softmax stats {max, inv}
__device__ float  g_attn_scratch[(size_t)B_ * S_ * S_];
__device__ float2 g_stats[(size_t)B_ * S_];

// pack two f32 -> f16x2 (lo = first element), round-to-nearest
__device__ __forceinline__ uint32_t f2h2(float lo, float hi) {
    uint32_t r;
    asm("cvt.rn.f16x2.f32 %0, %1, %2;" : "=r"(r) : "f"(hi), "f"(lo));
    return r;
}

__device__ __forceinline__ void mma_f16(float* c, const uint32_t* a, const uint32_t* b) {
    asm volatile(
        "mma.sync.aligned.m16n8k16.row.col.f32.f16.f16.f32 "
        "{%0,%1,%2,%3}, {%4,%5,%6,%7}, {%8,%9}, {%0,%1,%2,%3};\n"
        : "+f"(c[0]), "+f"(c[1]), "+f"(c[2]), "+f"(c[3])
        : "r"(a[0]), "r"(a[1]), "r"(a[2]), "r"(a[3]),
          "r"(b[0]), "r"(b[1]));
}
__device__ __forceinline__ void ldsm4(uint32_t& r0, uint32_t& r1, uint32_t& r2, uint32_t& r3, uint32_t a) {
    asm volatile("ldmatrix.sync.aligned.m8n8.x4.shared.b16 {%0,%1,%2,%3}, [%4];"
                 : "=r"(r0), "=r"(r1), "=r"(r2), "=r"(r3) : "r"(a));
}
__device__ __forceinline__ void ldsm2(uint32_t& r0, uint32_t& r1, uint32_t a) {
    asm volatile("ldmatrix.sync.aligned.m8n8.x2.shared.b16 {%0,%1}, [%2];"
                 : "=r"(r0), "=r"(r1) : "r"(a));
}
__device__ __forceinline__ void ldsm2t(uint32_t& r0, uint32_t& r1, uint32_t a) {
    asm volatile("ldmatrix.sync.aligned.m8n8.x2.trans.shared.b16 {%0,%1}, [%2];"
                 : "=r"(r0), "=r"(r1) : "r"(a));
}

// ---------------------------------------------------------------------------
// Kernel 1: masked_vec = (Q K^T)*SCALE*mask -> g_attn_scratch (lower+diag
// tiles).  Strict-upper tiles: zero-fill the attn OUTPUT (final values).
// 128x128 tile, BK=64, fp16 m16n8k16, 3-stage smem ring (R13/R16 structure).
// ---------------------------------------------------------------------------
__global__ __launch_bounds__(256, 2) void qk_kernel(
    const float* __restrict__ Q, const float* __restrict__ K,
    const int* __restrict__ rep, float* __restrict__ attn_out)
{
    const int bm = blockIdx.y, bn = blockIdx.x, b = blockIdx.z;
    const int m0 = bm * 128, n0 = bn * 128;
    const int tid = threadIdx.x;

    if (bn > bm) {
        if (attn_out) {                       // final zeros for strict-upper
            float* ab = attn_out + (size_t)b * S_ * S_;
            float4 z = make_float4(0.f, 0.f, 0.f, 0.f);
            #pragma unroll
            for (int i = 0; i < 16; i++) {
                int idx = tid + i * 256;
                int r = idx >> 5, c = idx & 31;
                reinterpret_cast<float4*>(ab + (size_t)(m0 + r) * S_ + n0)[c] = z;
            }
        }
        return;
    }
    float* attn_b = g_attn_scratch + (size_t)b * S_ * S_;

    extern __shared__ float smem[];              // 3 stages x 32KB (A16K + B16K)
    const uint32_t smem_u = (uint32_t)__cvta_generic_to_shared(smem);

    const int warp = tid >> 5, lane = tid & 31;
    const int wm = warp & 1, wn = warp >> 1;
    const int gID = lane >> 2, tig = lane & 3;

    const float* Qb = Q + ((size_t)b * S_ + m0) * D_;
    const float* Kb = K + ((size_t)b * S_ + n0) * D_;

    const int lr = tid >> 3, lc = tid & 7;
    const uint32_t psw = (uint32_t)((lc ^ (lr & 7)) << 4);

    const int l7 = lane & 7;
    const int lb1 = (lane >> 3) & 1;
    const int lb2 = lane >> 4;

    float acc[4][4][4];
    #pragma unroll
    for (int i = 0; i < 4; i++)
        #pragma unroll
        for (int j = 0; j < 4; j++)
            #pragma unroll
            for (int r = 0; r < 4; r++) acc[i][j][r] = 0.f;

    uint4 qh[4], kh[4];

    #define QK_LDG(kk) do {                                                    \
        _Pragma("unroll")                                                      \
        for (int i_ = 0; i_ < 4; i_++) {                                       \
            int r_ = lr + i_ * 32;                                             \
            const float* pq = Qb + (size_t)r_ * D_ + (kk) + lc * 8;            \
            float4 x = *reinterpret_cast<const float4*>(pq);                   \
            float4 y = *reinterpret_cast<const float4*>(pq + 4);               \
            qh[i_].x = f2h2(x.x, x.y); qh[i_].y = f2h2(x.z, x.w);              \
            qh[i_].z = f2h2(y.x, y.y); qh[i_].w = f2h2(y.z, y.w);              \
            const float* pk = Kb + (size_t)r_ * D_ + (kk) + lc * 8;            \
            x = *reinterpret_cast<const float4*>(pk);                          \
            y = *reinterpret_cast<const float4*>(pk + 4);                      \
            kh[i_].x = f2h2(x.x, x.y); kh[i_].y = f2h2(x.z, x.w);              \
            kh[i_].z = f2h2(y.x, y.y); kh[i_].w = f2h2(y.z, y.w);              \
        }                                                                      \
    } while (0)

    #define QK_STS(st) do {                                                    \
        uint32_t bA_ = smem_u + (uint32_t)(st) * 32768u;                       \
        uint32_t bB_ = bA_ + 16384u;                                           \
        _Pragma("unroll")                                                      \
        for (int i_ = 0; i_ < 4; i_++) {                                       \
            uint32_t off_ = (uint32_t)((lr + i_ * 32) * 128) + psw;            \
            asm volatile("st.shared.v4.b32 [%0], {%1,%2,%3,%4};" ::            \
                "r"(bA_ + off_), "r"(qh[i_].x), "r"(qh[i_].y),                 \
                "r"(qh[i_].z), "r"(qh[i_].w) : "memory");                      \
            asm volatile("st.shared.v4.b32 [%0], {%1,%2,%3,%4};" ::            \
                "r"(bB_ + off_), "r"(kh[i_].x), "r"(kh[i_].y),                 \
                "r"(kh[i_].z), "r"(kh[i_].w) : "memory");                      \
        }                                                                      \
    } while (0)

    QK_LDG(0);
    QK_STS(0);
    QK_LDG(64);
    __syncthreads();

    for (int t = 0; t < 8; t++) {                // D/64 = 8 k-tiles
        const uint32_t bA = smem_u + (uint32_t)(t % 3) * 32768u;
        const uint32_t bB = bA + 16384u;

        if (t + 1 < 8) {
            QK_STS((t + 1) % 3);
            if (t + 2 < 8) QK_LDG((t + 2) * 64);
        }

        #pragma unroll
        for (int ks = 0; ks < 4; ks++) {         // 4 x k16 per tile
            uint32_t bf[4][2];
            #pragma unroll
            for (int in_ = 0; in_ < 4; in_++) {
                int n = wn * 32 + in_ * 8 + l7;
                uint32_t addr = bB + (uint32_t)(n * 128)
                              + (uint32_t)((((ks << 1) + lb1) ^ l7) << 4);
                ldsm2(bf[in_][0], bf[in_][1], addr);
            }
            #pragma unroll
            for (int im = 0; im < 4; im++) {
                int r = wm * 64 + im * 16 + l7 + lb1 * 8;
                uint32_t addr = bA + (uint32_t)(r * 128)
                              + (uint32_t)((((ks << 1) + lb2) ^ l7) << 4);
                uint32_t a[4];
                ldsm4(a[0], a[1], a[2], a[3], addr);
                #pragma unroll
                for (int in_ = 0; in_ < 4; in_++)
                    mma_f16(acc[im][in_], a, bf[in_]);
            }
        }
        __syncthreads();
    }
    #undef QK_LDG
    #undef QK_STS

    // Epilogue: scale + mask, write masked_vec to scratch.
    const int* repb = rep + b * S_;
    #pragma unroll
    for (int im = 0; im < 4; im++) {
        int mA = m0 + wm * 64 + im * 16 + gID;
        int mB = mA + 8;
        int rqA = repb[mA], rqB = repb[mB];
        #pragma unroll
        for (int in_ = 0; in_ < 4; in_++) {
            int n = n0 + wn * 32 + in_ * 8 + tig * 2;
            int rk0 = repb[n], rk1 = repb[n + 1];
            float v00 = acc[im][in_][0] * SCALE;
            float v01 = acc[im][in_][1] * SCALE;
            float v10 = acc[im][in_][2] * SCALE;
            float v11 = acc[im][in_][3] * SCALE;
            attn_b[(size_t)mA * S_ + n]     = (n     < mA && rqA && rk0) ? v00 : 0.f;
            attn_b[(size_t)mA * S_ + n + 1] = (n + 1 < mA && rqA && rk1) ? v01 : 0.f;
            attn_b[(size_t)mB * S_ + n]     = (n     < mB && rqB && rk0) ? v10 : 0.f;
            attn_b[(size_t)mB * S_ + n + 1] = (n + 1 < mB && rqB && rk1) ? v11 : 0.f;
        }
    }
}

// ---------------------------------------------------------------------------
// Kernel 2: stats only (warp-per-row, triangular READ of scratch, no write-
// back).  g_stats[b,q] = {row max (incl structural zeros), 1/(s+(s==0)+1e-20)}.
// ---------------------------------------------------------------------------
__global__ __launch_bounds__(256) void stats_kernel(const int* __restrict__ rep)
{
    const int b = blockIdx.y;
    const int warp = threadIdx.x >> 5, lane = threadIdx.x & 31;
    const int q = blockIdx.x * 8 + warp;

    __shared__ int rk_s[S_];
    reinterpret_cast<int4*>(rk_s)[threadIdx.x] =
        reinterpret_cast<const int4*>(rep + (size_t)b * S_)[threadIdx.x];
    __syncthreads();

    const float* row = g_attn_scratch + ((size_t)b * S_ + q) * S_;
    const int rq = rk_s[q];
    const int nch = (q + 127) >> 7;      // 128-float chunks covering k < q

    float4 v[8];
    float mx = 0.f;                      // structural zeros are in every row
    #pragma unroll
    for (int c = 0; c < 8; c++) {
        if (c < nch) {
            v[c] = reinterpret_cast<const float4*>(row)[c * 32 + lane];
            mx = fmaxf(mx, fmaxf(fmaxf(v[c].x, v[c].y), fmaxf(v[c].z, v[c].w)));
        }
    }
    #pragma unroll
    for (int o = 16; o; o >>= 1) mx = fmaxf(mx, __shfl_xor_sync(0xffffffffu, mx, o));

    float sum = 0.f;
    #pragma unroll
    for (int c = 0; c < 8; c++) {
        if (c < nch) {
            const int k0 = c * 128 + lane * 4;
            float e0 = (k0     < q && rq && rk_s[k0])     ? __expf(v[c].x - mx) : 0.f;
            float e1 = (k0 + 1 < q && rq && rk_s[k0 + 1]) ? __expf(v[c].y - mx) : 0.f;
            float e2 = (k0 + 2 < q && rq && rk_s[k0 + 2]) ? __expf(v[c].z - mx) : 0.f;
            float e3 = (k0 + 3 < q && rq && rk_s[k0 + 3]) ? __expf(v[c].w - mx) : 0.f;
            sum += (e0 + e1) + (e2 + e3);
        }
    }
    #pragma unroll
    for (int o = 16; o; o >>= 1) sum += __shfl_xor_sync(0xffffffffu, sum, o);

    float s2 = sum + ((sum == 0.f) ? 1.f : 0.f);
    float inv = 1.f / (s2 + 1e-20f);

    if (lane == 0) g_stats[(size_t)b * S_ + q] = make_float2(mx, inv);
}

// ---------------------------------------------------------------------------
// Kernel 3: out = softmax(masked_vec) @ V, softmax applied on the fly in the
// A-producer (e = mask ? exp(v-mx) : 0; a = e*inv).  bn==0 CTA also streams
// the normalized f32 values into the attn output (by-product).
// Heavy tiles first: bm = 7 - blockIdx.y.
// ---------------------------------------------------------------------------
__global__ __launch_bounds__(256, 2) void pv_kernel(
    const float* __restrict__ V, const int* __restrict__ rep,
    float* __restrict__ attn_out, float* __restrict__ out)
{
    const int bm = 7 - blockIdx.y;               // heavy (long) tiles first
    const int bn = blockIdx.x, b = blockIdx.z;
    const int m0 = bm * 128, n0 = bn * 128;
    const int tid = threadIdx.x;

    extern __shared__ float smem[];  // [0,96KB) 3 stages; then rep(4KB)+stats(1KB)
    const uint32_t smem_u = (uint32_t)__cvta_generic_to_shared(smem);
    int*    rep_s   = reinterpret_cast<int*>(smem + 24576);
    float2* stats_s = reinterpret_cast<float2*>(smem + 25600);

    const int warp = tid >> 5, lane = tid & 31;
    const int wm = warp & 1, wn = warp >> 1;
    const int gID = lane >> 2, tig = lane & 3;

    const float* Ab = g_attn_scratch + ((size_t)b * S_ + m0) * S_;
    const float* Vb = V + (size_t)b * S_ * D_;
    const bool wattn = (attn_out != nullptr) && (bn == 0);

    // cache rep row + row stats
    reinterpret_cast<int4*>(rep_s)[tid] =
        reinterpret_cast<const int4*>(rep + (size_t)b * S_)[tid];
    if (tid < 128) stats_s[tid] = g_stats[(size_t)b * S_ + m0 + tid];
    __syncthreads();

    const int lr = tid >> 3, lc = tid & 7;
    const uint32_t psw = (uint32_t)((lc ^ (lr & 7)) << 4);
    const int vr = tid >> 4, vc = tid & 15;
    const uint32_t vsw = (uint32_t)((vc ^ (vr & 7)) << 4);

    const int l7 = lane & 7;
    const int lb1 = (lane >> 3) & 1;
    const int lb2 = lane >> 4;

    float acc[4][4][4];
    #pragma unroll
    for (int i = 0; i < 4; i++)
        #pragma unroll
        for (int j = 0; j < 4; j++)
            #pragma unroll
            for (int r = 0; r < 4; r++) acc[i][j][r] = 0.f;

    const int NT = (bm + 1) * 2;     // k-tiles of 64 f32, strictly-lower bound

    uint4 ah[4], vh[4];

    #define PV_LDG(kk) do {                                                    \
        const int c0_ = (kk) + lc * 8;                                         \
        const int4 rka_ = *reinterpret_cast<const int4*>(rep_s + c0_);         \
        const int4 rkb_ = *reinterpret_cast<const int4*>(rep_s + c0_ + 4);     \
        _Pragma("unroll")                                                      \
        for (int i_ = 0; i_ < 4; i_++) {                                       \
            int r_ = lr + i_ * 32;                                             \
            int qrow_ = m0 + r_;                                               \
            const float* pa = Ab + (size_t)r_ * S_ + c0_;                      \
            float4 x = *reinterpret_cast<const float4*>(pa);                   \
            float4 y = *reinterpret_cast<const float4*>(pa + 4);               \
            float2 st_ = stats_s[r_];                                          \
            int rq_ = rep_s[qrow_];                                            \
            float e0 = (c0_     < qrow_ && rq_ && rka_.x) ? __expf(x.x - st_.x) * st_.y : 0.f; \
            float e1 = (c0_ + 1 < qrow_ && rq_ && rka_.y) ? __expf(x.y - st_.x) * st_.y : 0.f; \
            float e2 = (c0_ + 2 < qrow_ && rq_ && rka_.z) ? __expf(x.z - st_.x) * st_.y : 0.f; \
            float e3 = (c0_ + 3 < qrow_ && rq_ && rka_.w) ? __expf(x.w - st_.x) * st_.y : 0.f; \
            float e4 = (c0_ + 4 < qrow_ && rq_ && rkb_.x) ? __expf(y.x - st_.x) * st_.y : 0.f; \
            float e5 = (c0_ + 5 < qrow_ && rq_ && rkb_.y) ? __expf(y.y - st_.x) * st_.y : 0.f; \
            float e6 = (c0_ + 6 < qrow_ && rq_ && rkb_.z) ? __expf(y.z - st_.x) * st_.y : 0.f; \
            float e7 = (c0_ + 7 < qrow_ && rq_ && rkb_.w) ? __expf(y.w - st_.x) * st_.y : 0.f; \
            if (wattn) {                                                       \
                float* ap = attn_out + ((size_t)b * S_ + qrow_) * S_ + c0_;    \
                *reinterpret_cast<float4*>(ap)     = make_float4(e0, e1, e2, e3); \
                *reinterpret_cast<float4*>(ap + 4) = make_float4(e4, e5, e6, e7); \
            }                                                                  \
            ah[i_].x = f2h2(e0, e1); ah[i_].y = f2h2(e2, e3);                  \
            ah[i_].z = f2h2(e4, e5); ah[i_].w = f2h2(e6, e7);                  \
            int kr_ = vr + i_ * 16;                                            \
            const float* pv = Vb + (size_t)((kk) + kr_) * D_ + n0 + vc * 8;    \
            x = *reinterpret_cast<const float4*>(pv);                          \
            y = *reinterpret_cast<const float4*>(pv + 4);                      \
            vh[i_].x = f2h2(x.x, x.y); vh[i_].y = f2h2(x.z, x.w);              \
            vh[i_].z = f2h2(y.x, y.y); vh[i_].w = f2h2(y.z, y.w);              \
        }                                                                      \
    } while (0)

    #define PV_STS(st) do {                                                    \
        uint32_t bA_ = smem_u + (uint32_t)(st) * 32768u;                       \
        uint32_t bV_ = bA_ + 16384u;                                           \
        _Pragma("unroll")                                                      \
        for (int i_ = 0; i_ < 4; i_++) {                                       \
            uint32_t offA_ = (uint32_t)((lr + i_ * 32) * 128) + psw;           \
            asm volatile("st.shared.v4.b32 [%0], {%1,%2,%3,%4};" ::            \
                "r"(bA_ + offA_), "r"(ah[i_].x), "r"(ah[i_].y),                \
                "r"(ah[i_].z), "r"(ah[i_].w) : "memory");                      \
            uint32_t offV_ = (uint32_t)((vr + i_ * 16) * 256) + vsw;           \
            asm volatile("st.shared.v4.b32 [%0], {%1,%2,%3,%4};" ::            \
                "r"(bV_ + offV_), "r"(vh[i_].x), "r"(vh[i_].y),                \
                "r"(vh[i_].z), "r"(vh[i_].w) : "memory");                      \
        }                                                                      \
    } while (0)

    PV_LDG(0);
    PV_STS(0);
    PV_LDG(64);                      // NT >= 2 always
    __syncthreads();

    for (int t = 0; t < NT; t++) {
        const uint32_t bA = smem_u + (uint32_t)(t % 3) * 32768u;
        const uint32_t bV = bA + 16384u;

        if (t + 1 < NT) {
            PV_STS((t + 1) % 3);
            if (t + 2 < NT) PV_LDG((t + 2) * 64);
        }

        #pragma unroll
        for (int ks = 0; ks < 4; ks++) {
            uint32_t bf[4][2];
            #pragma unroll
            for (int in_ = 0; in_ < 4; in_++) {
                int nch = wn * 4 + in_;
                int kr = ks * 16 + l7 + lb1 * 8;
                uint32_t addr = bV + (uint32_t)(kr * 256)
                              + (uint32_t)((nch ^ l7) << 4);
                ldsm2t(bf[in_][0], bf[in_][1], addr);
            }
            #pragma unroll
            for (int im = 0; im < 4; im++) {
                int r = wm * 64 + im * 16 + l7 + lb1 * 8;
                uint32_t addr = bA + (uint32_t)(r * 128)
                              + (uint32_t)((((ks << 1) + lb2) ^ l7) << 4);
                uint32_t a[4];
                ldsm4(a[0], a[1], a[2], a[3], addr);
                #pragma unroll
                for (int in_ = 0; in_ < 4; in_++)
                    mma_f16(acc[im][in_], a, bf[in_]);
            }
        }
        __syncthreads();
    }
    #undef PV_LDG
    #undef PV_STS

    #pragma unroll
    for (int im = 0; im < 4; im++) {
        int mA = m0 + wm * 64 + im * 16 + gID;
        int mB = mA + 8;
        #pragma unroll
        for (int in_ = 0; in_ < 4; in_++) {
            int n = n0 + wn * 32 + in_ * 8 + tig * 2;
            out[((size_t)b * S_ + mA) * D_ + n]     = acc[im][in_][0];
            out[((size_t)b * S_ + mA) * D_ + n + 1] = acc[im][in_][1];
            out[((size_t)b * S_ + mB) * D_ + n]     = acc[im][in_][2];
            out[((size_t)b * S_ + mB) * D_ + n + 1] = acc[im][in_][3];
        }
    }
}

extern "C" void kernel_launch(void* const* d_in, const int* in_sizes, int n_in,
                              void* d_out, int out_size)
{
    const float* q   = (const float*)d_in[0];
    const float* k   = (const float*)d_in[1];
    const float* v   = (const float*)d_in[2];
    const int*   rep = (const int*)d_in[3];
    float* out = (float*)d_out;

    const long OUT_ELEMS  = (long)B_ * S_ * D_;   // 16,777,216
    const long ATTN_ELEMS = (long)B_ * S_ * S_;   // 33,554,432

    float* attn = nullptr;
    if ((long)out_size >= OUT_ELEMS + ATTN_ELEMS)
        attn = out + OUT_ELEMS;

    const int QK_SMEM = 3 * 32768;            // 98304 B
    const int PV_SMEM = 3 * 32768 + 5120;     // + rep(4KB) + stats(1KB)
    cudaFuncSetAttribute(qk_kernel, cudaFuncAttributeMaxDynamicSharedMemorySize, QK_SMEM);
    cudaFuncSetAttribute(pv_kernel, cudaFuncAttributeMaxDynamicSharedMemorySize, PV_SMEM);

    dim3 g1(8, 8, B_);
    qk_kernel<<<g1, 256, QK_SMEM>>>(q, k, rep, attn);

    dim3 g2(S_ / 8, B_);
    stats_kernel<<<g2, 256>>>(rep);

    dim3 g3(4, 8, B_);
    pv_kernel<<<g3, 256, PV_SMEM>>>(v, rep, attn, out);
}